// round 16
// baseline (speedup 1.0000x reference)
#include <cuda_runtime.h>
#include <cuda_fp16.h>
#include <cstdint>

#define NN 100000
#define EE 1600000

// ---------------- scratch (device globals; no allocation allowed) ----------------
__device__ __half g_Bh0[256 * 128];                // layer0 [Wl|Wr], N-major fp16
__device__ __half g_Bh1[256 * 128];                // layer1
__device__ __half g_Bh2[128 * 128];                // layer2
__device__ __half g_T[(size_t)NN * 128];           // GEMM out T-part (h@Wl), fp16
__device__ __half g_R[(size_t)NN * 128];           // GEMM out R-part (h@Wr), fp16
__device__ __half g_h[(size_t)NN * 128];           // hidden activations, fp16
__device__ float  g_inv[NN];                       // 1 / max(deg, 1)
__device__ int    g_degi[NN];
__device__ int    g_off[NN + 1];                   // CSR offsets (by dst)
__device__ int    g_cursor[NN];
__device__ int    g_csr[EE];                       // src ids grouped by dst
__device__ int    g_bsum[256];                     // per-block scan sums
__device__ int    g_is64;

__device__ __forceinline__ uint32_t h2_to_u32(__half2 h) {
    return *reinterpret_cast<uint32_t*>(&h);
}

// ---------------- init: zero degrees + dtype detect ----------------
__global__ void init_kernel(const int* __restrict__ ei32, int n) {
    int i = blockIdx.x * blockDim.x + threadIdx.x;
    if (i < n) g_degi[i] = 0;
    if (i == 0) {
        int is64 = 1;
        for (int q = 0; q < 64; q++) {
            if (ei32[2 * q + 1] != 0) { is64 = 0; break; }
        }
        g_is64 = is64;
    }
}

// degree histogram (reads dst half of edge index only)
__global__ void deg_kernel(const void* __restrict__ ei, int E, int N) {
    int e = blockIdx.x * blockDim.x + threadIdx.x;
    if (e >= E) return;
    int d;
    if (g_is64) d = (int)((const long long*)ei)[(size_t)E + e];
    else        d = ((const int*)ei)[E + e];
    d = min(max(d, 0), N - 1);
    atomicAdd(&g_degi[d], 1);
}

// ---------------- parallel 3-phase exclusive scan ----------------
__global__ __launch_bounds__(1024) void scan_local_kernel(int n) {
    __shared__ int warp_sums[32];
    const int lane = threadIdx.x & 31;
    const int wid  = threadIdx.x >> 5;
    int i = blockIdx.x * 1024 + threadIdx.x;
    int v = (i < n) ? g_degi[i] : 0;
    int x = v;
#pragma unroll
    for (int o = 1; o < 32; o <<= 1) {
        int y = __shfl_up_sync(0xffffffffu, x, o);
        if (lane >= o) x += y;
    }
    if (lane == 31) warp_sums[wid] = x;
    __syncthreads();
    if (wid == 0) {
        int w = warp_sums[lane];
#pragma unroll
        for (int o = 1; o < 32; o <<= 1) {
            int y = __shfl_up_sync(0xffffffffu, w, o);
            if (lane >= o) w += y;
        }
        warp_sums[lane] = w;
    }
    __syncthreads();
    int incl = x + (wid > 0 ? warp_sums[wid - 1] : 0);
    if (i < n) g_off[i] = incl - v;  // block-local exclusive
    if (threadIdx.x == 1023) g_bsum[blockIdx.x] = incl;
}

// parallel scan of up to 128 block sums
__global__ void scan_bsums_kernel(int nb, int n) {
    __shared__ int ws[4];
    const int i = threadIdx.x;        // 0..127
    const int lane = i & 31;
    const int w = i >> 5;
    int v = (i < nb) ? g_bsum[i] : 0;
    int x = v;
#pragma unroll
    for (int o = 1; o < 32; o <<= 1) {
        int y = __shfl_up_sync(0xffffffffu, x, o);
        if (lane >= o) x += y;
    }
    if (lane == 31) ws[w] = x;
    __syncthreads();
    int woff = 0;
#pragma unroll
    for (int q = 0; q < 4; q++) if (q < w) woff += ws[q];
    int incl = x + woff;
    if (i < nb) g_bsum[i] = incl - v;   // exclusive
    if (i == 127) g_off[n] = incl;      // grand total
}

__global__ __launch_bounds__(1024) void scan_add_kernel(int n) {
    int i = blockIdx.x * 1024 + threadIdx.x;
    if (i >= n) return;
    int off = g_off[i] + g_bsum[blockIdx.x];
    g_off[i] = off;
    g_cursor[i] = off;
    g_inv[i] = 1.0f / fmaxf((float)g_degi[i], 1.0f);
}

// fill CSR: re-decode edge index directly (no src/dst intermediates)
__global__ void csr_fill_kernel(const void* __restrict__ ei, int E, int N) {
    int e = blockIdx.x * blockDim.x + threadIdx.x;
    if (e >= E) return;
    int s, d;
    if (g_is64) {
        const long long* p = (const long long*)ei;
        s = (int)p[e];
        d = (int)p[(size_t)E + e];
    } else {
        const int* p = (const int*)ei;
        s = p[e];
        d = p[E + e];
    }
    s = min(max(s, 0), N - 1);
    d = min(max(d, 0), N - 1);
    int pos = atomicAdd(&g_cursor[d], 1);
    g_csr[pos] = s;
}

// all three layers' weights -> fp16, N-major g_Bh*[j][k], one kernel
__global__ void concat_all_kernel(
    const float* __restrict__ Wl0, const float* __restrict__ Wr0,
    const float* __restrict__ Wl1, const float* __restrict__ Wr1,
    const float* __restrict__ Wl2, const float* __restrict__ Wr2) {
    int id = blockIdx.x * blockDim.x + threadIdx.x;
    if (id < 32768) {
        int j = id >> 7, k = id & 127;
        float v = (j < 128) ? Wl0[k * 128 + j] : Wr0[k * 128 + (j - 128)];
        g_Bh0[id] = __float2half_rn(v);
    } else if (id < 65536) {
        int t2 = id - 32768;
        int j = t2 >> 7, k = t2 & 127;
        float v = (j < 128) ? Wl1[k * 128 + j] : Wr1[k * 128 + (j - 128)];
        g_Bh1[t2] = __float2half_rn(v);
    } else if (id < 81920) {
        int t2 = id - 65536;
        int j = t2 >> 7, k = t2 & 127;
        float v = (j < 64) ? Wl2[k * 64 + j] : Wr2[k * 64 + (j - 64)];
        g_Bh2[t2] = __float2half_rn(v);
    }
}

// ---------------- fp16 tensor-core GEMM (double-buffered + ldmatrix) ----------------
// C[N,W] = A[N,128] @ B[128,W]; T half of columns -> g_T, R half -> g_R (both fp16).
// 128x128 block tile, 8 warps of 32(M)x64(N), mma.m16n8k16 f16.f16.f32.
template<int W, bool USE_H, int LAYER>
__global__ __launch_bounds__(256) void gemm_tc_kernel(const float* __restrict__ Aext, int nrows) {
    constexpr int DOUT = W / 2;
    __shared__ __half As[2][128][40];
    __shared__ __half Bs[2][128][40];

    const __half* __restrict__ Bw =
        (LAYER == 0) ? (const __half*)g_Bh0 :
        (LAYER == 1) ? (const __half*)g_Bh1 : (const __half*)g_Bh2;

    const int bm = blockIdx.x * 128;
    const int bn = blockIdx.y * 128;
    const int t = threadIdx.x;
    const int lane = t & 31;
    const int wid = t >> 5;
    const int warpM = wid & 3;
    const int warpN = wid >> 2;
    const int g = lane >> 2;
    const int tig = lane & 3;
    const int lmat = lane >> 3;        // 0..3 (ldmatrix matrix index)
    const int l7 = lane & 7;           // row within matrix

    const int srow = t >> 1;
    const int skoff = (t & 1) * 16;

    float acc[2][8][4];
#pragma unroll
    for (int mt = 0; mt < 2; mt++)
#pragma unroll
        for (int nt = 0; nt < 8; nt++)
#pragma unroll
            for (int c = 0; c < 4; c++) acc[mt][nt][c] = 0.f;

    const bool arow_ok = (bm + srow) < nrows;
    const float*  afptr = Aext ? (Aext + (size_t)(bm + srow) * 128 + skoff) : nullptr;
    const __half* ahptr = (const __half*)g_h + (size_t)(bm + srow) * 128 + skoff;
    const __half* bptr  = Bw + (size_t)(bn + srow) * 128 + skoff;

    uint4 aStage[2];
    uint4 bReg[2];

    auto loadA = [&](int kc) {
        if (USE_H) {
            if (arow_ok) {
                aStage[0] = *reinterpret_cast<const uint4*>(ahptr + kc);
                aStage[1] = *reinterpret_cast<const uint4*>(ahptr + kc + 8);
            } else {
                aStage[0] = make_uint4(0, 0, 0, 0);
                aStage[1] = make_uint4(0, 0, 0, 0);
            }
        } else {
            float4 f[4];
#pragma unroll
            for (int i = 0; i < 4; i++)
                f[i] = arow_ok ? *reinterpret_cast<const float4*>(afptr + kc + i * 4)
                               : make_float4(0.f, 0.f, 0.f, 0.f);
            aStage[0].x = h2_to_u32(__floats2half2_rn(f[0].x, f[0].y));
            aStage[0].y = h2_to_u32(__floats2half2_rn(f[0].z, f[0].w));
            aStage[0].z = h2_to_u32(__floats2half2_rn(f[1].x, f[1].y));
            aStage[0].w = h2_to_u32(__floats2half2_rn(f[1].z, f[1].w));
            aStage[1].x = h2_to_u32(__floats2half2_rn(f[2].x, f[2].y));
            aStage[1].y = h2_to_u32(__floats2half2_rn(f[2].z, f[2].w));
            aStage[1].z = h2_to_u32(__floats2half2_rn(f[3].x, f[3].y));
            aStage[1].w = h2_to_u32(__floats2half2_rn(f[3].z, f[3].w));
        }
    };
    auto loadB = [&](int kc) {
        bReg[0] = *reinterpret_cast<const uint4*>(bptr + kc);
        bReg[1] = *reinterpret_cast<const uint4*>(bptr + kc + 8);
    };
    auto stage = [&](int buf) {
        *reinterpret_cast<uint4*>(&As[buf][srow][skoff])     = aStage[0];
        *reinterpret_cast<uint4*>(&As[buf][srow][skoff + 8]) = aStage[1];
        *reinterpret_cast<uint4*>(&Bs[buf][srow][skoff])     = bReg[0];
        *reinterpret_cast<uint4*>(&Bs[buf][srow][skoff + 8]) = bReg[1];
    };

    // prologue: chunk 0 -> buf 0
    loadA(0);
    loadB(0);
    stage(0);
    __syncthreads();

#pragma unroll
    for (int it = 0; it < 4; it++) {
        const int cur = it & 1;
        // issue global prefetch of next chunk (latency covered by MMA below)
        if (it < 3) {
            loadA((it + 1) * 32);
            loadB((it + 1) * 32);
        }

#pragma unroll
        for (int ks = 0; ks < 2; ks++) {
            const int kk = ks * 16;
            uint32_t a[2][4], b[8][2];
            // A fragments via ldmatrix.x4: matrices
            // [m0..7,kk..+7],[m0+8..,kk..+7],[m0..7,kk+8..],[m0+8..,kk+8..]
#pragma unroll
            for (int mt = 0; mt < 2; mt++) {
                const __half* pa = &As[cur][warpM * 32 + mt * 16 + (lmat & 1) * 8 + l7]
                                      [kk + (lmat >> 1) * 8];
                uint32_t sa = (uint32_t)__cvta_generic_to_shared(pa);
                asm volatile(
                    "ldmatrix.sync.aligned.m8n8.x4.shared.b16 {%0,%1,%2,%3}, [%4];"
                    : "=r"(a[mt][0]), "=r"(a[mt][1]), "=r"(a[mt][2]), "=r"(a[mt][3])
                    : "r"(sa));
            }
            // B fragments via ldmatrix.x2: matrices [n0..7,kk..+7],[n0..7,kk+8..]
#pragma unroll
            for (int nt = 0; nt < 8; nt++) {
                const __half* pb = &Bs[cur][warpN * 64 + nt * 8 + l7]
                                      [kk + ((lane >> 3) & 1) * 8];
                uint32_t sb = (uint32_t)__cvta_generic_to_shared(pb);
                asm volatile(
                    "ldmatrix.sync.aligned.m8n8.x2.shared.b16 {%0,%1}, [%2];"
                    : "=r"(b[nt][0]), "=r"(b[nt][1])
                    : "r"(sb));
            }
#pragma unroll
            for (int mt = 0; mt < 2; mt++)
#pragma unroll
                for (int nt = 0; nt < 8; nt++) {
                    asm volatile(
                        "mma.sync.aligned.m16n8k16.row.col.f32.f16.f16.f32 "
                        "{%0,%1,%2,%3}, {%4,%5,%6,%7}, {%8,%9}, {%0,%1,%2,%3};"
                        : "+f"(acc[mt][nt][0]), "+f"(acc[mt][nt][1]),
                          "+f"(acc[mt][nt][2]), "+f"(acc[mt][nt][3])
                        : "r"(a[mt][0]), "r"(a[mt][1]), "r"(a[mt][2]), "r"(a[mt][3]),
                          "r"(b[nt][0]), "r"(b[nt][1]));
                }
        }

        // stage next chunk into the other buffer
        if (it < 3) stage(cur ^ 1);
        __syncthreads();
    }

    // store: both halves fp16; warp's 64-wide range aligns with DOUT multiples.
    const int gn0 = bn + warpN * 64;
    __half* obase = (gn0 < DOUT) ? (g_T + gn0) : (g_R + (gn0 - DOUT));
#pragma unroll
    for (int mt = 0; mt < 2; mt++) {
        int mrow0 = bm + warpM * 32 + mt * 16 + g;
#pragma unroll
        for (int hf = 0; hf < 2; hf++) {
            int row = mrow0 + hf * 8;
            if (row < nrows) {
                __half* orow = obase + (size_t)row * DOUT;
#pragma unroll
                for (int nt = 0; nt < 8; nt++) {
                    __half2 hv = __floats2half2_rn(acc[mt][nt][hf * 2 + 0],
                                                   acc[mt][nt][hf * 2 + 1]);
                    *reinterpret_cast<__half2*>(&orow[nt * 8 + 2 * tig]) = hv;
                }
            }
        }
    }
}

// ---------------- fused gather + epilogue: warp per dst node ----------------
// out[node] = (sum_{src} g_T[src]) * inv + bl + g_R[node]  [+ BN + ReLU]
template<int DOUT, bool DO_BN, bool TO_OUT>
__global__ __launch_bounds__(256) void gather_kernel(
    const float* __restrict__ bl,
    const float* __restrict__ bng, const float* __restrict__ bnb,
    const float* __restrict__ bnm, const float* __restrict__ bnv,
    float* __restrict__ out, int n) {
    constexpr int F = DOUT / 32;  // values per lane: 4 or 2
    int node = blockIdx.x * (blockDim.x >> 5) + (threadIdx.x >> 5);
    if (node >= n) return;
    int lane = threadIdx.x & 31;
    const int col = lane * F;

    float acc[F];
#pragma unroll
    for (int f = 0; f < F; f++) acc[f] = 0.f;

    int p = g_off[node];
    const int end = g_off[node + 1];

    // unroll by 4 for memory-level parallelism
    for (; p + 4 <= end; p += 4) {
        int s0 = g_csr[p], s1 = g_csr[p + 1], s2 = g_csr[p + 2], s3 = g_csr[p + 3];
        if (F == 4) {
            uint2 r0 = *reinterpret_cast<const uint2*>(&g_T[(size_t)s0 * DOUT + col]);
            uint2 r1 = *reinterpret_cast<const uint2*>(&g_T[(size_t)s1 * DOUT + col]);
            uint2 r2 = *reinterpret_cast<const uint2*>(&g_T[(size_t)s2 * DOUT + col]);
            uint2 r3 = *reinterpret_cast<const uint2*>(&g_T[(size_t)s3 * DOUT + col]);
#pragma unroll
            for (int q = 0; q < 4; q++) {
                uint2 r = (q == 0) ? r0 : (q == 1) ? r1 : (q == 2) ? r2 : r3;
                float2 a0 = __half22float2(*reinterpret_cast<__half2*>(&r.x));
                float2 a1 = __half22float2(*reinterpret_cast<__half2*>(&r.y));
                acc[0] += a0.x; acc[1] += a0.y; acc[2] += a1.x; acc[3] += a1.y;
            }
        } else {
            __half2 h0 = *reinterpret_cast<const __half2*>(&g_T[(size_t)s0 * DOUT + col]);
            __half2 h1 = *reinterpret_cast<const __half2*>(&g_T[(size_t)s1 * DOUT + col]);
            __half2 h2 = *reinterpret_cast<const __half2*>(&g_T[(size_t)s2 * DOUT + col]);
            __half2 h3 = *reinterpret_cast<const __half2*>(&g_T[(size_t)s3 * DOUT + col]);
            float2 a0 = __half22float2(h0), a1 = __half22float2(h1);
            float2 a2 = __half22float2(h2), a3 = __half22float2(h3);
            acc[0] += a0.x + a1.x + a2.x + a3.x;
            acc[1] += a0.y + a1.y + a2.y + a3.y;
        }
    }
    for (; p < end; p++) {
        int s0 = g_csr[p];
        if (F == 4) {
            uint2 r0 = *reinterpret_cast<const uint2*>(&g_T[(size_t)s0 * DOUT + col]);
            float2 a0 = __half22float2(*reinterpret_cast<__half2*>(&r0.x));
            float2 a1 = __half22float2(*reinterpret_cast<__half2*>(&r0.y));
            acc[0] += a0.x; acc[1] += a0.y; acc[2] += a1.x; acc[3] += a1.y;
        } else {
            __half2 h0 = *reinterpret_cast<const __half2*>(&g_T[(size_t)s0 * DOUT + col]);
            float2 a0 = __half22float2(h0);
            acc[0] += a0.x; acc[1] += a0.y;
        }
    }

    const float inv = g_inv[node];
    float o[F];
    float rv[F];
    {
        const __half* rrow = &g_R[(size_t)node * DOUT + col];
        if (F == 4) {
            uint2 r = *reinterpret_cast<const uint2*>(rrow);
            float2 a0 = __half22float2(*reinterpret_cast<__half2*>(&r.x));
            float2 a1 = __half22float2(*reinterpret_cast<__half2*>(&r.y));
            rv[0] = a0.x; rv[1] = a0.y; rv[2] = a1.x; rv[3] = a1.y;
        } else {
            float2 a0 = __half22float2(*reinterpret_cast<const __half2*>(rrow));
            rv[0] = a0.x; rv[1] = a0.y;
        }
    }
#pragma unroll
    for (int f = 0; f < F; f++)
        o[f] = acc[f] * inv + bl[col + f] + rv[f];

    if (DO_BN) {
#pragma unroll
        for (int f = 0; f < F; f++) {
            float gm = bng[col + f], bt = bnb[col + f];
            float mm = bnm[col + f], vv = bnv[col + f];
            o[f] = fmaxf((o[f] - mm) * (gm * rsqrtf(vv + 1e-5f)) + bt, 0.f);
        }
    }

    if (TO_OUT) {
        float* wptr = &out[(size_t)node * DOUT + col];
        if (F == 4)
            *reinterpret_cast<float4*>(wptr) = make_float4(o[0], o[1], o[2], o[3]);
        else
            *reinterpret_cast<float2*>(wptr) = make_float2(o[0], o[1]);
    } else {
        __half* wptr = &g_h[(size_t)node * DOUT + col];
        if (F == 4) {
            uint2 u;
            u.x = h2_to_u32(__floats2half2_rn(o[0], o[1]));
            u.y = h2_to_u32(__floats2half2_rn(o[2], o[3]));
            *reinterpret_cast<uint2*>(wptr) = u;
        } else {
            *reinterpret_cast<__half2*>(wptr) = __floats2half2_rn(o[0], o[1]);
        }
    }
}

// ---------------- launch ----------------
extern "C" void kernel_launch(void* const* d_in, const int* in_sizes, int n_in,
                              void* d_out, int out_size) {
    const float* x   = (const float*)d_in[0];
    const void*  ei  = d_in[1];
    const float* Wl0 = (const float*)d_in[2];
    const float* Wr0 = (const float*)d_in[3];
    const float* bl0 = (const float*)d_in[4];
    const float* Wl1 = (const float*)d_in[5];
    const float* Wr1 = (const float*)d_in[6];
    const float* bl1 = (const float*)d_in[7];
    const float* Wl2 = (const float*)d_in[8];
    const float* Wr2 = (const float*)d_in[9];
    const float* bl2 = (const float*)d_in[10];
    const float* g0 = (const float*)d_in[11];
    const float* b0 = (const float*)d_in[12];
    const float* m0 = (const float*)d_in[13];
    const float* v0 = (const float*)d_in[14];
    const float* g1 = (const float*)d_in[15];
    const float* b1 = (const float*)d_in[16];
    const float* m1 = (const float*)d_in[17];
    const float* v1 = (const float*)d_in[18];
    float* out = (float*)d_out;

    const int N = in_sizes[0] / 128;
    const int E = in_sizes[1] / 2;
    const int nb = (N + 1023) / 1024;

    // one-time side stream + fork/join events (host objects, no device memory)
    static cudaStream_t s_side = nullptr;
    static cudaEvent_t  s_fork = nullptr, s_join = nullptr;
    if (s_side == nullptr) {
        cudaStreamCreateWithFlags(&s_side, cudaStreamNonBlocking);
        cudaEventCreateWithFlags(&s_fork, cudaEventDisableTiming);
        cudaEventCreateWithFlags(&s_join, cudaEventDisableTiming);
    }

    // ---- fork: CSR build on side stream, weights+GEMM0 on main ----
    cudaEventRecord(s_fork, 0);
    cudaStreamWaitEvent(s_side, s_fork, 0);

    init_kernel<<<(N + 255) / 256, 256, 0, s_side>>>((const int*)ei, N);
    deg_kernel<<<(E + 255) / 256, 256, 0, s_side>>>(ei, E, N);
    scan_local_kernel<<<nb, 1024, 0, s_side>>>(N);
    scan_bsums_kernel<<<1, 128, 0, s_side>>>(nb, N);
    scan_add_kernel<<<nb, 1024, 0, s_side>>>(N);
    csr_fill_kernel<<<(E + 255) / 256, 256, 0, s_side>>>(ei, E, N);
    cudaEventRecord(s_join, s_side);

    dim3 gemmGridWide((N + 127) / 128, 2);
    dim3 gemmGridNarrow((N + 127) / 128, 1);
    int gatherBlocks = (N + 7) / 8;  // 8 warps per block

    concat_all_kernel<<<(81920 + 255) / 256, 256>>>(Wl0, Wr0, Wl1, Wr1, Wl2, Wr2);
    gemm_tc_kernel<256, false, 0><<<gemmGridWide, 256>>>(x, N);

    // ---- join: gather-0 needs CSR + GEMM0 ----
    cudaStreamWaitEvent(0, s_join, 0);
    gather_kernel<128, true, false><<<gatherBlocks, 256>>>(bl0, g0, b0, m0, v0, nullptr, N);

    // ---- layer 1: g_h -> g_h (BN + ReLU) ----
    gemm_tc_kernel<256, true, 1><<<gemmGridWide, 256>>>(nullptr, N);
    gather_kernel<128, true, false><<<gatherBlocks, 256>>>(bl1, g1, b1, m1, v1, nullptr, N);

    // ---- layer 2: g_h -> out (no BN/ReLU) ----
    gemm_tc_kernel<128, true, 2><<<gemmGridNarrow, 256>>>(nullptr, N);
    gather_kernel<64, false, true><<<gatherBlocks, 256>>>(bl2, nullptr, nullptr, nullptr, nullptr, out, N);
}

// round 17
// speedup vs baseline: 1.0881x; 1.0881x over previous
#include <cuda_runtime.h>
#include <cuda_fp16.h>
#include <cstdint>

#define NN 100000
#define EE 1600000

// ---------------- scratch (device globals; no allocation allowed) ----------------
__device__ __half g_Bh0[256 * 128];                // layer0 [Wl|Wr], N-major fp16
__device__ __half g_Bh1[256 * 128];                // layer1
__device__ __half g_Bh2[128 * 128];                // layer2
__device__ __half g_T[(size_t)NN * 128];           // GEMM out T-part (h@Wl), fp16
__device__ __half g_R[(size_t)NN * 128];           // GEMM out R-part (h@Wr), fp16
__device__ __half g_h[(size_t)NN * 128];           // hidden activations, fp16
__device__ float  g_inv[NN];                       // 1 / max(deg, 1)
__device__ int    g_degi[NN];
__device__ int    g_off[NN + 1];                   // CSR offsets (by dst)
__device__ int    g_cursor[NN];
__device__ int    g_csr[EE];                       // src ids grouped by dst
__device__ int    g_bsum[256];                     // per-block scan sums
__device__ int    g_is64;

__device__ __forceinline__ uint32_t h2_to_u32(__half2 h) {
    return *reinterpret_cast<uint32_t*>(&h);
}

__device__ __forceinline__ void cp16(uint32_t dst_smem, const void* src) {
    asm volatile("cp.async.ca.shared.global [%0], [%1], 16;"
                 :: "r"(dst_smem), "l"(src));
}

// ---------------- init: zero degrees + dtype detect ----------------
__global__ void init_kernel(const int* __restrict__ ei32, int n) {
    int i = blockIdx.x * blockDim.x + threadIdx.x;
    if (i < n) g_degi[i] = 0;
    if (i == 0) {
        int is64 = 1;
        for (int q = 0; q < 64; q++) {
            if (ei32[2 * q + 1] != 0) { is64 = 0; break; }
        }
        g_is64 = is64;
    }
}

// degree histogram (reads dst half of edge index only)
__global__ void deg_kernel(const void* __restrict__ ei, int E, int N) {
    int e = blockIdx.x * blockDim.x + threadIdx.x;
    if (e >= E) return;
    int d;
    if (g_is64) d = (int)((const long long*)ei)[(size_t)E + e];
    else        d = ((const int*)ei)[E + e];
    d = min(max(d, 0), N - 1);
    atomicAdd(&g_degi[d], 1);
}

// ---------------- parallel 3-phase exclusive scan ----------------
__global__ __launch_bounds__(1024) void scan_local_kernel(int n) {
    __shared__ int warp_sums[32];
    const int lane = threadIdx.x & 31;
    const int wid  = threadIdx.x >> 5;
    int i = blockIdx.x * 1024 + threadIdx.x;
    int v = (i < n) ? g_degi[i] : 0;
    int x = v;
#pragma unroll
    for (int o = 1; o < 32; o <<= 1) {
        int y = __shfl_up_sync(0xffffffffu, x, o);
        if (lane >= o) x += y;
    }
    if (lane == 31) warp_sums[wid] = x;
    __syncthreads();
    if (wid == 0) {
        int w = warp_sums[lane];
#pragma unroll
        for (int o = 1; o < 32; o <<= 1) {
            int y = __shfl_up_sync(0xffffffffu, w, o);
            if (lane >= o) w += y;
        }
        warp_sums[lane] = w;
    }
    __syncthreads();
    int incl = x + (wid > 0 ? warp_sums[wid - 1] : 0);
    if (i < n) g_off[i] = incl - v;  // block-local exclusive
    if (threadIdx.x == 1023) g_bsum[blockIdx.x] = incl;
}

// parallel scan of up to 128 block sums
__global__ void scan_bsums_kernel(int nb, int n) {
    __shared__ int ws[4];
    const int i = threadIdx.x;        // 0..127
    const int lane = i & 31;
    const int w = i >> 5;
    int v = (i < nb) ? g_bsum[i] : 0;
    int x = v;
#pragma unroll
    for (int o = 1; o < 32; o <<= 1) {
        int y = __shfl_up_sync(0xffffffffu, x, o);
        if (lane >= o) x += y;
    }
    if (lane == 31) ws[w] = x;
    __syncthreads();
    int woff = 0;
#pragma unroll
    for (int q = 0; q < 4; q++) if (q < w) woff += ws[q];
    int incl = x + woff;
    if (i < nb) g_bsum[i] = incl - v;   // exclusive
    if (i == 127) g_off[n] = incl;      // grand total
}

__global__ __launch_bounds__(1024) void scan_add_kernel(int n) {
    int i = blockIdx.x * 1024 + threadIdx.x;
    if (i >= n) return;
    int off = g_off[i] + g_bsum[blockIdx.x];
    g_off[i] = off;
    g_cursor[i] = off;
    g_inv[i] = 1.0f / fmaxf((float)g_degi[i], 1.0f);
}

// fill CSR: re-decode edge index directly (no src/dst intermediates)
__global__ void csr_fill_kernel(const void* __restrict__ ei, int E, int N) {
    int e = blockIdx.x * blockDim.x + threadIdx.x;
    if (e >= E) return;
    int s, d;
    if (g_is64) {
        const long long* p = (const long long*)ei;
        s = (int)p[e];
        d = (int)p[(size_t)E + e];
    } else {
        const int* p = (const int*)ei;
        s = p[e];
        d = p[E + e];
    }
    s = min(max(s, 0), N - 1);
    d = min(max(d, 0), N - 1);
    int pos = atomicAdd(&g_cursor[d], 1);
    g_csr[pos] = s;
}

// all three layers' weights -> fp16, N-major g_Bh*[j][k], one kernel
__global__ void concat_all_kernel(
    const float* __restrict__ Wl0, const float* __restrict__ Wr0,
    const float* __restrict__ Wl1, const float* __restrict__ Wr1,
    const float* __restrict__ Wl2, const float* __restrict__ Wr2) {
    int id = blockIdx.x * blockDim.x + threadIdx.x;
    if (id < 32768) {
        int j = id >> 7, k = id & 127;
        float v = (j < 128) ? Wl0[k * 128 + j] : Wr0[k * 128 + (j - 128)];
        g_Bh0[id] = __float2half_rn(v);
    } else if (id < 65536) {
        int t2 = id - 32768;
        int j = t2 >> 7, k = t2 & 127;
        float v = (j < 128) ? Wl1[k * 128 + j] : Wr1[k * 128 + (j - 128)];
        g_Bh1[t2] = __float2half_rn(v);
    } else if (id < 81920) {
        int t2 = id - 65536;
        int j = t2 >> 7, k = t2 & 127;
        float v = (j < 64) ? Wl2[k * 64 + j] : Wr2[k * 64 + (j - 64)];
        g_Bh2[t2] = __float2half_rn(v);
    }
}

// ---------------- fp16 tensor-core GEMM (double-buffered + cp.async staging) ----------------
// C[N,W] = A[N,128] @ B[128,W]; T half of columns -> g_T, R half -> g_R (both fp16).
// 128x128 block tile, 8 warps of 32(M)x64(N), mma.m16n8k16 f16.f16.f32.
// Fragment loads: scalar LDS (R14-proven). Staging: cp.async (B always; A when fp16).
template<int W, bool USE_H, int LAYER>
__global__ __launch_bounds__(256) void gemm_tc_kernel(const float* __restrict__ Aext, int nrows) {
    constexpr int DOUT = W / 2;
    __shared__ __half As[2][128][40];
    __shared__ __half Bs[2][128][40];

    const __half* __restrict__ Bw =
        (LAYER == 0) ? (const __half*)g_Bh0 :
        (LAYER == 1) ? (const __half*)g_Bh1 : (const __half*)g_Bh2;

    const int bm = blockIdx.x * 128;
    const int bn = blockIdx.y * 128;
    const int t = threadIdx.x;
    const int lane = t & 31;
    const int wid = t >> 5;
    const int warpM = wid & 3;
    const int warpN = wid >> 2;
    const int g = lane >> 2;
    const int tig = lane & 3;

    const int srow = t >> 1;
    const int skoff = (t & 1) * 16;

    float acc[2][8][4];
#pragma unroll
    for (int mt = 0; mt < 2; mt++)
#pragma unroll
        for (int nt = 0; nt < 8; nt++)
#pragma unroll
            for (int c = 0; c < 4; c++) acc[mt][nt][c] = 0.f;

    const bool arow_ok = (bm + srow) < nrows;
    const int arow_clamped = min(bm + srow, nrows - 1);  // cp.async path: dup row, never stored
    const float*  afptr = Aext ? (Aext + (size_t)(bm + srow) * 128 + skoff) : nullptr;
    const __half* ahptr = (const __half*)g_h + (size_t)arow_clamped * 128 + skoff;
    const __half* bptr  = Bw + (size_t)(bn + srow) * 128 + skoff;

    // shared destinations for this thread's staging slice
    uint32_t sA[2], sB[2];
    sA[0] = (uint32_t)__cvta_generic_to_shared(&As[0][srow][skoff]);
    sA[1] = (uint32_t)__cvta_generic_to_shared(&As[1][srow][skoff]);
    sB[0] = (uint32_t)__cvta_generic_to_shared(&Bs[0][srow][skoff]);
    sB[1] = (uint32_t)__cvta_generic_to_shared(&Bs[1][srow][skoff]);

    uint4 aStage[2];   // register path for layer-0 A (fp32 -> fp16 convert)

    auto loadA_f32 = [&](int kc) {
        float4 f[4];
#pragma unroll
        for (int i = 0; i < 4; i++)
            f[i] = arow_ok ? *reinterpret_cast<const float4*>(afptr + kc + i * 4)
                           : make_float4(0.f, 0.f, 0.f, 0.f);
        aStage[0].x = h2_to_u32(__floats2half2_rn(f[0].x, f[0].y));
        aStage[0].y = h2_to_u32(__floats2half2_rn(f[0].z, f[0].w));
        aStage[0].z = h2_to_u32(__floats2half2_rn(f[1].x, f[1].y));
        aStage[0].w = h2_to_u32(__floats2half2_rn(f[1].z, f[1].w));
        aStage[1].x = h2_to_u32(__floats2half2_rn(f[2].x, f[2].y));
        aStage[1].y = h2_to_u32(__floats2half2_rn(f[2].z, f[2].w));
        aStage[1].z = h2_to_u32(__floats2half2_rn(f[3].x, f[3].y));
        aStage[1].w = h2_to_u32(__floats2half2_rn(f[3].z, f[3].w));
    };
    auto stageA_f32 = [&](int buf) {
        *reinterpret_cast<uint4*>(&As[buf][srow][skoff])     = aStage[0];
        *reinterpret_cast<uint4*>(&As[buf][srow][skoff + 8]) = aStage[1];
    };
    auto cpA = [&](int buf, int kc) {
        cp16(sA[buf],      ahptr + kc);
        cp16(sA[buf] + 16, ahptr + kc + 8);
    };
    auto cpB = [&](int buf, int kc) {
        cp16(sB[buf],      bptr + kc);
        cp16(sB[buf] + 16, bptr + kc + 8);
    };

    // prologue: chunk 0 -> buf 0
    cpB(0, 0);
    if (USE_H) {
        cpA(0, 0);
    } else {
        loadA_f32(0);
        stageA_f32(0);
    }
    asm volatile("cp.async.commit_group;" ::: "memory");
    asm volatile("cp.async.wait_group 0;" ::: "memory");
    __syncthreads();

#pragma unroll
    for (int it = 0; it < 4; it++) {
        const int cur = it & 1;
        // issue async prefetch of next chunk into the other buffer
        if (it < 3) {
            cpB(cur ^ 1, (it + 1) * 32);
            if (USE_H) cpA(cur ^ 1, (it + 1) * 32);
            else       loadA_f32((it + 1) * 32);
            asm volatile("cp.async.commit_group;" ::: "memory");
        }

#pragma unroll
        for (int ks = 0; ks < 2; ks++) {
            const int kk = ks * 16;
            uint32_t a[2][4], b[8][2];
#pragma unroll
            for (int mt = 0; mt < 2; mt++) {
                int m0 = warpM * 32 + mt * 16 + g;
                a[mt][0] = *reinterpret_cast<const uint32_t*>(&As[cur][m0][kk + 2 * tig]);
                a[mt][1] = *reinterpret_cast<const uint32_t*>(&As[cur][m0 + 8][kk + 2 * tig]);
                a[mt][2] = *reinterpret_cast<const uint32_t*>(&As[cur][m0][kk + 2 * tig + 8]);
                a[mt][3] = *reinterpret_cast<const uint32_t*>(&As[cur][m0 + 8][kk + 2 * tig + 8]);
            }
#pragma unroll
            for (int nt = 0; nt < 8; nt++) {
                int n0 = warpN * 64 + nt * 8 + g;
                b[nt][0] = *reinterpret_cast<const uint32_t*>(&Bs[cur][n0][kk + 2 * tig]);
                b[nt][1] = *reinterpret_cast<const uint32_t*>(&Bs[cur][n0][kk + 2 * tig + 8]);
            }
#pragma unroll
            for (int mt = 0; mt < 2; mt++)
#pragma unroll
                for (int nt = 0; nt < 8; nt++) {
                    asm volatile(
                        "mma.sync.aligned.m16n8k16.row.col.f32.f16.f16.f32 "
                        "{%0,%1,%2,%3}, {%4,%5,%6,%7}, {%8,%9}, {%0,%1,%2,%3};"
                        : "+f"(acc[mt][nt][0]), "+f"(acc[mt][nt][1]),
                          "+f"(acc[mt][nt][2]), "+f"(acc[mt][nt][3])
                        : "r"(a[mt][0]), "r"(a[mt][1]), "r"(a[mt][2]), "r"(a[mt][3]),
                          "r"(b[nt][0]), "r"(b[nt][1]));
                }
        }

        if (it < 3) {
            if (!USE_H) stageA_f32(cur ^ 1);
            asm volatile("cp.async.wait_group 0;" ::: "memory");
        }
        __syncthreads();
    }

    // store: both halves fp16; warp's 64-wide range aligns with DOUT multiples.
    const int gn0 = bn + warpN * 64;
    __half* obase = (gn0 < DOUT) ? (g_T + gn0) : (g_R + (gn0 - DOUT));
#pragma unroll
    for (int mt = 0; mt < 2; mt++) {
        int mrow0 = bm + warpM * 32 + mt * 16 + g;
#pragma unroll
        for (int hf = 0; hf < 2; hf++) {
            int row = mrow0 + hf * 8;
            if (row < nrows) {
                __half* orow = obase + (size_t)row * DOUT;
#pragma unroll
                for (int nt = 0; nt < 8; nt++) {
                    __half2 hv = __floats2half2_rn(acc[mt][nt][hf * 2 + 0],
                                                   acc[mt][nt][hf * 2 + 1]);
                    *reinterpret_cast<__half2*>(&orow[nt * 8 + 2 * tig]) = hv;
                }
            }
        }
    }
}

// ---------------- fused gather + epilogue: warp per dst node ----------------
// out[node] = (sum_{src} g_T[src]) * inv + bl + g_R[node]  [+ BN + ReLU]
template<int DOUT, bool DO_BN, bool TO_OUT>
__global__ __launch_bounds__(256) void gather_kernel(
    const float* __restrict__ bl,
    const float* __restrict__ bng, const float* __restrict__ bnb,
    const float* __restrict__ bnm, const float* __restrict__ bnv,
    float* __restrict__ out, int n) {
    constexpr int F = DOUT / 32;  // values per lane: 4 or 2
    int node = blockIdx.x * (blockDim.x >> 5) + (threadIdx.x >> 5);
    if (node >= n) return;
    int lane = threadIdx.x & 31;
    const int col = lane * F;

    float acc[F];
#pragma unroll
    for (int f = 0; f < F; f++) acc[f] = 0.f;

    int p = g_off[node];
    const int end = g_off[node + 1];

    // unroll by 4 for memory-level parallelism
    for (; p + 4 <= end; p += 4) {
        int s0 = g_csr[p], s1 = g_csr[p + 1], s2 = g_csr[p + 2], s3 = g_csr[p + 3];
        if (F == 4) {
            uint2 r0 = *reinterpret_cast<const uint2*>(&g_T[(size_t)s0 * DOUT + col]);
            uint2 r1 = *reinterpret_cast<const uint2*>(&g_T[(size_t)s1 * DOUT + col]);
            uint2 r2 = *reinterpret_cast<const uint2*>(&g_T[(size_t)s2 * DOUT + col]);
            uint2 r3 = *reinterpret_cast<const uint2*>(&g_T[(size_t)s3 * DOUT + col]);
#pragma unroll
            for (int q = 0; q < 4; q++) {
                uint2 r = (q == 0) ? r0 : (q == 1) ? r1 : (q == 2) ? r2 : r3;
                float2 a0 = __half22float2(*reinterpret_cast<__half2*>(&r.x));
                float2 a1 = __half22float2(*reinterpret_cast<__half2*>(&r.y));
                acc[0] += a0.x; acc[1] += a0.y; acc[2] += a1.x; acc[3] += a1.y;
            }
        } else {
            __half2 h0 = *reinterpret_cast<const __half2*>(&g_T[(size_t)s0 * DOUT + col]);
            __half2 h1 = *reinterpret_cast<const __half2*>(&g_T[(size_t)s1 * DOUT + col]);
            __half2 h2 = *reinterpret_cast<const __half2*>(&g_T[(size_t)s2 * DOUT + col]);
            __half2 h3 = *reinterpret_cast<const __half2*>(&g_T[(size_t)s3 * DOUT + col]);
            float2 a0 = __half22float2(h0), a1 = __half22float2(h1);
            float2 a2 = __half22float2(h2), a3 = __half22float2(h3);
            acc[0] += a0.x + a1.x + a2.x + a3.x;
            acc[1] += a0.y + a1.y + a2.y + a3.y;
        }
    }
    for (; p < end; p++) {
        int s0 = g_csr[p];
        if (F == 4) {
            uint2 r0 = *reinterpret_cast<const uint2*>(&g_T[(size_t)s0 * DOUT + col]);
            float2 a0 = __half22float2(*reinterpret_cast<__half2*>(&r0.x));
            float2 a1 = __half22float2(*reinterpret_cast<__half2*>(&r0.y));
            acc[0] += a0.x; acc[1] += a0.y; acc[2] += a1.x; acc[3] += a1.y;
        } else {
            __half2 h0 = *reinterpret_cast<const __half2*>(&g_T[(size_t)s0 * DOUT + col]);
            float2 a0 = __half22float2(h0);
            acc[0] += a0.x; acc[1] += a0.y;
        }
    }

    const float inv = g_inv[node];
    float o[F];
    float rv[F];
    {
        const __half* rrow = &g_R[(size_t)node * DOUT + col];
        if (F == 4) {
            uint2 r = *reinterpret_cast<const uint2*>(rrow);
            float2 a0 = __half22float2(*reinterpret_cast<__half2*>(&r.x));
            float2 a1 = __half22float2(*reinterpret_cast<__half2*>(&r.y));
            rv[0] = a0.x; rv[1] = a0.y; rv[2] = a1.x; rv[3] = a1.y;
        } else {
            float2 a0 = __half22float2(*reinterpret_cast<const __half2*>(rrow));
            rv[0] = a0.x; rv[1] = a0.y;
        }
    }
#pragma unroll
    for (int f = 0; f < F; f++)
        o[f] = acc[f] * inv + bl[col + f] + rv[f];

    if (DO_BN) {
#pragma unroll
        for (int f = 0; f < F; f++) {
            float gm = bng[col + f], bt = bnb[col + f];
            float mm = bnm[col + f], vv = bnv[col + f];
            o[f] = fmaxf((o[f] - mm) * (gm * rsqrtf(vv + 1e-5f)) + bt, 0.f);
        }
    }

    if (TO_OUT) {
        float* wptr = &out[(size_t)node * DOUT + col];
        if (F == 4)
            *reinterpret_cast<float4*>(wptr) = make_float4(o[0], o[1], o[2], o[3]);
        else
            *reinterpret_cast<float2*>(wptr) = make_float2(o[0], o[1]);
    } else {
        __half* wptr = &g_h[(size_t)node * DOUT + col];
        if (F == 4) {
            uint2 u;
            u.x = h2_to_u32(__floats2half2_rn(o[0], o[1]));
            u.y = h2_to_u32(__floats2half2_rn(o[2], o[3]));
            *reinterpret_cast<uint2*>(wptr) = u;
        } else {
            *reinterpret_cast<__half2*>(wptr) = __floats2half2_rn(o[0], o[1]);
        }
    }
}

// ---------------- launch ----------------
extern "C" void kernel_launch(void* const* d_in, const int* in_sizes, int n_in,
                              void* d_out, int out_size) {
    const float* x   = (const float*)d_in[0];
    const void*  ei  = d_in[1];
    const float* Wl0 = (const float*)d_in[2];
    const float* Wr0 = (const float*)d_in[3];
    const float* bl0 = (const float*)d_in[4];
    const float* Wl1 = (const float*)d_in[5];
    const float* Wr1 = (const float*)d_in[6];
    const float* bl1 = (const float*)d_in[7];
    const float* Wl2 = (const float*)d_in[8];
    const float* Wr2 = (const float*)d_in[9];
    const float* bl2 = (const float*)d_in[10];
    const float* g0 = (const float*)d_in[11];
    const float* b0 = (const float*)d_in[12];
    const float* m0 = (const float*)d_in[13];
    const float* v0 = (const float*)d_in[14];
    const float* g1 = (const float*)d_in[15];
    const float* b1 = (const float*)d_in[16];
    const float* m1 = (const float*)d_in[17];
    const float* v1 = (const float*)d_in[18];
    float* out = (float*)d_out;

    const int N = in_sizes[0] / 128;
    const int E = in_sizes[1] / 2;
    const int nb = (N + 1023) / 1024;

    // one-time side stream + fork/join events (host objects, no device memory)
    static cudaStream_t s_side = nullptr;
    static cudaEvent_t  s_fork = nullptr, s_join = nullptr;
    if (s_side == nullptr) {
        cudaStreamCreateWithFlags(&s_side, cudaStreamNonBlocking);
        cudaEventCreateWithFlags(&s_fork, cudaEventDisableTiming);
        cudaEventCreateWithFlags(&s_join, cudaEventDisableTiming);
    }

    // ---- fork: CSR build on side stream, weights+GEMM0 on main ----
    cudaEventRecord(s_fork, 0);
    cudaStreamWaitEvent(s_side, s_fork, 0);

    init_kernel<<<(N + 255) / 256, 256, 0, s_side>>>((const int*)ei, N);
    deg_kernel<<<(E + 255) / 256, 256, 0, s_side>>>(ei, E, N);
    scan_local_kernel<<<nb, 1024, 0, s_side>>>(N);
    scan_bsums_kernel<<<1, 128, 0, s_side>>>(nb, N);
    scan_add_kernel<<<nb, 1024, 0, s_side>>>(N);
    csr_fill_kernel<<<(E + 255) / 256, 256, 0, s_side>>>(ei, E, N);
    cudaEventRecord(s_join, s_side);

    dim3 gemmGridWide((N + 127) / 128, 2);
    dim3 gemmGridNarrow((N + 127) / 128, 1);
    int gatherBlocks = (N + 7) / 8;  // 8 warps per block

    concat_all_kernel<<<(81920 + 255) / 256, 256>>>(Wl0, Wr0, Wl1, Wr1, Wl2, Wr2);
    gemm_tc_kernel<256, false, 0><<<gemmGridWide, 256>>>(x, N);

    // ---- join: gather-0 needs CSR + GEMM0 ----
    cudaStreamWaitEvent(0, s_join, 0);
    gather_kernel<128, true, false><<<gatherBlocks, 256>>>(bl0, g0, b0, m0, v0, nullptr, N);

    // ---- layer 1: g_h -> g_h (BN + ReLU) ----
    gemm_tc_kernel<256, true, 1><<<gemmGridWide, 256>>>(nullptr, N);
    gather_kernel<128, true, false><<<gatherBlocks, 256>>>(bl1, g1, b1, m1, v1, nullptr, N);

    // ---- layer 2: g_h -> out (no BN/ReLU) ----
    gemm_tc_kernel<128, true, 2><<<gemmGridNarrow, 256>>>(nullptr, N);
    gather_kernel<64, false, true><<<gatherBlocks, 256>>>(bl2, nullptr, nullptr, nullptr, nullptr, out, N);
}